// round 4
// baseline (speedup 1.0000x reference)
#include <cuda_runtime.h>
#include <cstdint>

#define NTOK 4096
#define DIM  1024
#define NEXP 8
#define HID  4096
#define THR  0.3f

#define BM 128
#define BN 128
#define BK 16
#define STG 2176   // floats per stage (16 * 136)

// ---------------- scratch (static device memory; no allocs anywhere) ----------------
__device__ float g_c[NTOK * NEXP];
__device__ int   g_idx[NEXP][NTOK];
__device__ float g_wt[NEXP][NTOK];
__device__ int   g_cnt[NEXP];
__device__ float g_h[(size_t)NEXP * NTOK * HID];   // hidden activations (tf32-rounded)

// ---------------- helpers ----------------
__device__ __forceinline__ uint32_t f2tf(float f) {
    uint32_t u;
    asm("cvt.rna.tf32.f32 %0, %1;" : "=r"(u) : "f"(f));
    return u;
}
__device__ __forceinline__ float rnatf(float f) { return __uint_as_float(f2tf(f)); }

__device__ __forceinline__ void mma8(float* c, const uint32_t* a, const uint32_t* b) {
    asm volatile(
        "mma.sync.aligned.m16n8k8.row.col.f32.tf32.tf32.f32 "
        "{%0,%1,%2,%3}, {%4,%5,%6,%7}, {%8,%9}, {%0,%1,%2,%3};"
        : "+f"(c[0]), "+f"(c[1]), "+f"(c[2]), "+f"(c[3])
        : "r"(a[0]), "r"(a[1]), "r"(a[2]), "r"(a[3]), "r"(b[0]), "r"(b[1]));
}

__device__ __forceinline__ float gelu_exact(float v) {
    return 0.5f * v * (1.0f + erff(v * 0.70710678118654752f));
}

// ---------------- kernel 1: gate scores, combine weights, out init with sum(c*b2) ----------------
__global__ __launch_bounds__(256) void gate_kernel(
    const float* __restrict__ x, const float* __restrict__ wg,
    const float* __restrict__ bg, const float* __restrict__ b2,
    float* __restrict__ out)
{
    __shared__ float wgs[DIM * 9];
    int tid = threadIdx.x;
    for (int i = tid; i < DIM * NEXP; i += 256)
        wgs[(i >> 3) * 9 + (i & 7)] = wg[i];
    __syncthreads();

    int lane = tid & 31, wid = tid >> 5;
    int n = blockIdx.x * 8 + wid;

    float s[NEXP];
#pragma unroll
    for (int e = 0; e < NEXP; e++) s[e] = 0.f;

    const float* xr = x + (size_t)n * DIM;
    for (int k = lane; k < DIM; k += 32) {
        float xv = xr[k];
#pragma unroll
        for (int e = 0; e < NEXP; e++) s[e] += xv * wgs[k * 9 + e];
    }
#pragma unroll
    for (int e = 0; e < NEXP; e++)
#pragma unroll
        for (int o = 16; o; o >>= 1)
            s[e] += __shfl_xor_sync(0xffffffffu, s[e], o);

    float mx = -1e30f;
#pragma unroll
    for (int e = 0; e < NEXP; e++) { s[e] += bg[e]; mx = fmaxf(mx, s[e]); }
    float sum = 0.f;
#pragma unroll
    for (int e = 0; e < NEXP; e++) { s[e] = expf(s[e] - mx); sum += s[e]; }
    float inv = 1.f / sum;
#pragma unroll
    for (int e = 0; e < NEXP; e++) s[e] *= inv;

    if (lane == 0) {
        float* gs = out + (size_t)NTOK * DIM + (size_t)n * NEXP;
#pragma unroll
        for (int e = 0; e < NEXP; e++) gs[e] = s[e];
    }

    float msum = 0.f; int cnt = 0;
#pragma unroll
    for (int e = 0; e < NEXP; e++) if (s[e] >= THR) { msum += s[e]; cnt++; }
    int top1 = 0; float best = s[0];
#pragma unroll
    for (int e = 1; e < NEXP; e++) if (s[e] > best) { best = s[e]; top1 = e; }
    float dn = 1.f / (msum + 1e-6f);
    float c[NEXP];
#pragma unroll
    for (int e = 0; e < NEXP; e++)
        c[e] = cnt ? ((s[e] >= THR) ? s[e] * dn : 0.f) : ((e == top1) ? 1.f : 0.f);

    if (lane == 0) {
#pragma unroll
        for (int e = 0; e < NEXP; e++) g_c[n * NEXP + e] = c[e];
    }

    for (int d = lane; d < DIM; d += 32) {
        float a = 0.f;
#pragma unroll
        for (int e = 0; e < NEXP; e++) a += c[e] * b2[e * DIM + d];
        out[(size_t)n * DIM + d] = a;
    }
}

// ---------------- kernel 2: per-expert compaction, 1 CTA per expert, block-wide scan ----------------
__global__ __launch_bounds__(256) void compact_kernel()
{
    const int e = blockIdx.x;
    __shared__ int wsum[8];
    __shared__ int wbase[9];
    const int tid = threadIdx.x, lane = tid & 31, wid = tid >> 5;

    int base = 0;
#pragma unroll
    for (int c0 = 0; c0 < NTOK; c0 += 256) {
        int n = c0 + tid;
        float c = g_c[n * NEXP + e];
        unsigned m = __ballot_sync(0xffffffffu, c > 0.f);
        if (lane == 0) wsum[wid] = __popc(m);
        __syncthreads();
        if (tid == 0) {
            int acc = 0;
#pragma unroll
            for (int w = 0; w < 8; w++) { wbase[w] = acc; acc += wsum[w]; }
            wbase[8] = acc;
        }
        __syncthreads();
        if (c > 0.f) {
            int pos = base + wbase[wid] + __popc(m & ((1u << lane) - 1u));
            g_idx[e][pos] = n;
            g_wt[e][pos]  = c;
        }
        base += wbase[8];
        __syncthreads();
    }
    if (tid == 0) g_cnt[e] = base;
}

// =====================================================================================
// FFN GEMMs: 4 warps/CTA, warp tile 64x64, CTA tile 128x128, BK=16, double-buffered.
// =====================================================================================

// ---------------- kernel 3: grouped GEMM1: h = gelu(gather(ei) @ w1 + b1), rna-rounded ----------------
__global__ __launch_bounds__(128, 2) void ffn1_kernel(
    const float* __restrict__ ei, const float* __restrict__ w1,
    const float* __restrict__ b1)
{
    __shared__ float As[2 * STG];
    __shared__ float Bs[2 * STG];

    const int e  = blockIdx.z;
    const int me = g_cnt[e];
    const int mt = blockIdx.x;
    if (mt * BM >= me) return;
    const int n0 = blockIdx.y * BN;

    const int tid  = threadIdx.x;
    const int lane = tid & 31;
    const int wid  = tid >> 5;
    const int wm   = wid >> 1;
    const int wn   = wid & 1;
    const int g    = lane >> 2;
    const int t    = lane & 3;

    const int s0 = mt * BM + tid;
    const bool av = (s0 < me);
    const int tok = av ? g_idx[e][s0] : 0;
    const float* aptr = ei + ((size_t)e * NTOK + tok) * DIM;

    const int bk4 = wid * 4;
    const float* bptr = w1 + (size_t)e * DIM * HID + n0 + lane * 4;
    const int bofs = (lane >> 1) * 136 + 4 * (lane & 1);

    float acc[4][8][4];
#pragma unroll
    for (int a = 0; a < 4; a++)
#pragma unroll
        for (int b = 0; b < 8; b++)
#pragma unroll
            for (int q = 0; q < 4; q++) acc[a][b][q] = 0.f;

    float4 pa[4], pb[4];
#pragma unroll
    for (int q = 0; q < 4; q++)
        pa[q] = av ? *(const float4*)(aptr + 4 * q) : make_float4(0, 0, 0, 0);
#pragma unroll
    for (int i = 0; i < 4; i++)
        pb[i] = *(const float4*)(bptr + (size_t)(bk4 + i) * HID);

    // prime stage 0
#pragma unroll
    for (int q = 0; q < 4; q++) {
        As[(4 * q + 0) * 136 + tid] = rnatf(pa[q].x);
        As[(4 * q + 1) * 136 + tid] = rnatf(pa[q].y);
        As[(4 * q + 2) * 136 + tid] = rnatf(pa[q].z);
        As[(4 * q + 3) * 136 + tid] = rnatf(pa[q].w);
    }
#pragma unroll
    for (int i = 0; i < 4; i++) {
        float4 v = make_float4(rnatf(pb[i].x), rnatf(pb[i].y), rnatf(pb[i].z), rnatf(pb[i].w));
        *(float4*)(Bs + bofs + (bk4 + i) * 8) = v;
    }
    __syncthreads();

    const int KT = DIM / BK;   // 64
    for (int kt = 0; kt < KT; kt++) {
        const int cur = (kt & 1) * STG;
        const bool more = (kt + 1 < KT);
        if (more) {
            const float* ap = aptr + (kt + 1) * BK;
#pragma unroll
            for (int q = 0; q < 4; q++)
                pa[q] = av ? *(const float4*)(ap + 4 * q) : make_float4(0, 0, 0, 0);
            const float* bp = bptr + (size_t)(kt + 1) * BK * HID;
#pragma unroll
            for (int i = 0; i < 4; i++)
                pb[i] = *(const float4*)(bp + (size_t)(bk4 + i) * HID);
        }
#pragma unroll
        for (int ks = 0; ks < 2; ks++) {
            const int k0 = ks * 8;
            uint32_t af[4][4];
#pragma unroll
            for (int mi = 0; mi < 4; mi++) {
                int m = wm * 64 + mi * 16;
                af[mi][0] = __float_as_uint(As[cur + (k0 + t) * 136 + m + g]);
                af[mi][1] = __float_as_uint(As[cur + (k0 + t) * 136 + m + g + 8]);
                af[mi][2] = __float_as_uint(As[cur + (k0 + t + 4) * 136 + m + g]);
                af[mi][3] = __float_as_uint(As[cur + (k0 + t + 4) * 136 + m + g + 8]);
            }
#pragma unroll
            for (int ni = 0; ni < 8; ni++) {
                int G = wn * 8 + ni;
                uint32_t bf[2];
                bf[0] = __float_as_uint(Bs[cur + G * 136 + (k0 + t) * 8 + g]);
                bf[1] = __float_as_uint(Bs[cur + G * 136 + (k0 + t + 4) * 8 + g]);
#pragma unroll
                for (int mi = 0; mi < 4; mi++)
                    mma8(acc[mi][ni], af[mi], bf);
            }
        }
        if (more) {
            const int nxt = ((kt + 1) & 1) * STG;
#pragma unroll
            for (int q = 0; q < 4; q++) {
                As[nxt + (4 * q + 0) * 136 + tid] = rnatf(pa[q].x);
                As[nxt + (4 * q + 1) * 136 + tid] = rnatf(pa[q].y);
                As[nxt + (4 * q + 2) * 136 + tid] = rnatf(pa[q].z);
                As[nxt + (4 * q + 3) * 136 + tid] = rnatf(pa[q].w);
            }
#pragma unroll
            for (int i = 0; i < 4; i++) {
                float4 v = make_float4(rnatf(pb[i].x), rnatf(pb[i].y), rnatf(pb[i].z), rnatf(pb[i].w));
                *(float4*)(Bs + nxt + bofs + (bk4 + i) * 8) = v;
            }
        }
        __syncthreads();
    }

    // epilogue: +b1, exact GELU, rna-round, write hidden scratch
#pragma unroll
    for (int mi = 0; mi < 4; mi++) {
#pragma unroll
        for (int h2 = 0; h2 < 2; h2++) {
            int row = wm * 64 + mi * 16 + g + 8 * h2;
            int ss = mt * BM + row;
            if (ss < me) {
                float* hrow = g_h + ((size_t)e * NTOK + ss) * HID;
#pragma unroll
                for (int ni = 0; ni < 8; ni++) {
                    int col = n0 + wn * 64 + ni * 8 + 2 * t;
                    float v0 = acc[mi][ni][2 * h2 + 0] + b1[e * HID + col];
                    float v1 = acc[mi][ni][2 * h2 + 1] + b1[e * HID + col + 1];
                    float2 o = make_float2(rnatf(gelu_exact(v0)), rnatf(gelu_exact(v1)));
                    *(float2*)(hrow + col) = o;
                }
            }
        }
    }
}

// ---------------- kernel 4: grouped GEMM2: out[tok] += c * (h @ w2) ----------------
__global__ __launch_bounds__(128, 2) void ffn2_kernel(
    const float* __restrict__ w2, float* __restrict__ out)
{
    __shared__ float As[2 * STG];
    __shared__ float Bs[2 * STG];

    const int e  = blockIdx.z;
    const int me = g_cnt[e];
    const int mt = blockIdx.x;
    if (mt * BM >= me) return;
    const int n0 = blockIdx.y * BN;

    const int tid  = threadIdx.x;
    const int lane = tid & 31;
    const int wid  = tid >> 5;
    const int wm   = wid >> 1;
    const int wn   = wid & 1;
    const int g    = lane >> 2;
    const int t    = lane & 3;

    const int s0 = mt * BM + tid;
    const float* aptr = g_h + ((size_t)e * NTOK + s0) * HID;   // rows >= me: stale, discarded

    const int bk4 = wid * 4;
    const float* bptr = w2 + (size_t)e * HID * DIM + n0 + lane * 4;
    const int bofs = (lane >> 1) * 136 + 4 * (lane & 1);

    float acc[4][8][4];
#pragma unroll
    for (int a = 0; a < 4; a++)
#pragma unroll
        for (int b = 0; b < 8; b++)
#pragma unroll
            for (int q = 0; q < 4; q++) acc[a][b][q] = 0.f;

    float4 pa[4], pb[4];
#pragma unroll
    for (int q = 0; q < 4; q++) pa[q] = *(const float4*)(aptr + 4 * q);
#pragma unroll
    for (int i = 0; i < 4; i++) pb[i] = *(const float4*)(bptr + (size_t)(bk4 + i) * DIM);

    // prime stage 0 (A already tf32-rounded in g_h)
#pragma unroll
    for (int q = 0; q < 4; q++) {
        As[(4 * q + 0) * 136 + tid] = pa[q].x;
        As[(4 * q + 1) * 136 + tid] = pa[q].y;
        As[(4 * q + 2) * 136 + tid] = pa[q].z;
        As[(4 * q + 3) * 136 + tid] = pa[q].w;
    }
#pragma unroll
    for (int i = 0; i < 4; i++) {
        float4 v = make_float4(rnatf(pb[i].x), rnatf(pb[i].y), rnatf(pb[i].z), rnatf(pb[i].w));
        *(float4*)(Bs + bofs + (bk4 + i) * 8) = v;
    }
    __syncthreads();

    const int KT = HID / BK;   // 256
    for (int kt = 0; kt < KT; kt++) {
        const int cur = (kt & 1) * STG;
        const bool more = (kt + 1 < KT);
        if (more) {
            const float* ap = aptr + (kt + 1) * BK;
#pragma unroll
            for (int q = 0; q < 4; q++) pa[q] = *(const float4*)(ap + 4 * q);
            const float* bp = bptr + (size_t)(kt + 1) * BK * DIM;
#pragma unroll
            for (int i = 0; i < 4; i++) pb[i] = *(const float4*)(bp + (size_t)(bk4 + i) * DIM);
        }
#pragma unroll
        for (int ks = 0; ks < 2; ks++) {
            const int k0 = ks * 8;
            uint32_t af[4][4];
#pragma unroll
            for (int mi = 0; mi < 4; mi++) {
                int m = wm * 64 + mi * 16;
                af[mi][0] = __float_as_uint(As[cur + (k0 + t) * 136 + m + g]);
                af[mi][1] = __float_as_uint(As[cur + (k0 + t) * 136 + m + g + 8]);
                af[mi][2] = __float_as_uint(As[cur + (k0 + t + 4) * 136 + m + g]);
                af[mi][3] = __float_as_uint(As[cur + (k0 + t + 4) * 136 + m + g + 8]);
            }
#pragma unroll
            for (int ni = 0; ni < 8; ni++) {
                int G = wn * 8 + ni;
                uint32_t bf[2];
                bf[0] = __float_as_uint(Bs[cur + G * 136 + (k0 + t) * 8 + g]);
                bf[1] = __float_as_uint(Bs[cur + G * 136 + (k0 + t + 4) * 8 + g]);
#pragma unroll
                for (int mi = 0; mi < 4; mi++)
                    mma8(acc[mi][ni], af[mi], bf);
            }
        }
        if (more) {
            const int nxt = ((kt + 1) & 1) * STG;
#pragma unroll
            for (int q = 0; q < 4; q++) {
                As[nxt + (4 * q + 0) * 136 + tid] = pa[q].x;
                As[nxt + (4 * q + 1) * 136 + tid] = pa[q].y;
                As[nxt + (4 * q + 2) * 136 + tid] = pa[q].z;
                As[nxt + (4 * q + 3) * 136 + tid] = pa[q].w;
            }
#pragma unroll
            for (int i = 0; i < 4; i++) {
                float4 v = make_float4(rnatf(pb[i].x), rnatf(pb[i].y), rnatf(pb[i].z), rnatf(pb[i].w));
                *(float4*)(Bs + nxt + bofs + (bk4 + i) * 8) = v;
            }
        }
        __syncthreads();
    }

    // epilogue: scaled scatter-add into fused output
#pragma unroll
    for (int mi = 0; mi < 4; mi++) {
#pragma unroll
        for (int h2 = 0; h2 < 2; h2++) {
            int row = wm * 64 + mi * 16 + g + 8 * h2;
            int ss = mt * BM + row;
            if (ss < me) {
                int tok  = g_idx[e][ss];
                float wc = g_wt[e][ss];
                float* orow = out + (size_t)tok * DIM;
#pragma unroll
                for (int ni = 0; ni < 8; ni++) {
                    int col = n0 + wn * 64 + ni * 8 + 2 * t;
                    atomicAdd(orow + col,     wc * acc[mi][ni][2 * h2 + 0]);
                    atomicAdd(orow + col + 1, wc * acc[mi][ni][2 * h2 + 1]);
                }
            }
        }
    }
}

// ---------------- launch ----------------
extern "C" void kernel_launch(void* const* d_in, const int* in_sizes, int n_in,
                              void* d_out, int out_size)
{
    (void)in_sizes; (void)n_in; (void)out_size;
    const float* x  = (const float*)d_in[0];
    const float* ei = (const float*)d_in[1];
    const float* wg = (const float*)d_in[2];
    const float* bg = (const float*)d_in[3];
    const float* w1 = (const float*)d_in[4];
    const float* b1 = (const float*)d_in[5];
    const float* w2 = (const float*)d_in[6];
    const float* b2 = (const float*)d_in[7];
    float* out = (float*)d_out;

    gate_kernel<<<NTOK / 8, 256>>>(x, wg, bg, b2, out);
    compact_kernel<<<NEXP, 256>>>();
    ffn1_kernel<<<dim3(NTOK / BM, HID / BN, NEXP), 128>>>(ei, w1, b1);
    ffn2_kernel<<<dim3(NTOK / BM, DIM / BN, NEXP), 128>>>(w2, out);
}

// round 5
// speedup vs baseline: 1.2232x; 1.2232x over previous
#include <cuda_runtime.h>
#include <cstdint>

#define NTOK 4096
#define DIM  1024
#define NEXP 8
#define HID  4096
#define THR  0.3f

#define BM 128
#define BN 128
#define BK 16
#define STG 2176   // floats per B stage (16 * 136)

// ---------------- scratch (static device memory; no allocs anywhere) ----------------
__device__ float g_c[NTOK * NEXP];
__device__ int   g_idx[NEXP][NTOK];
__device__ float g_wt[NEXP][NTOK];
__device__ int   g_cnt[NEXP];
// fragment-layout A operands (see frag_off): tiles of 128 rows x 8 k
__device__ __align__(16) float g_af[(size_t)NEXP * NTOK * DIM];   // gathered+rounded expert inputs
__device__ __align__(16) float g_hf[(size_t)NEXP * NTOK * HID];   // gelu hidden, rounded

// ---------------- helpers ----------------
__device__ __forceinline__ uint32_t f2tf(float f) {
    uint32_t u;
    asm("cvt.rna.tf32.f32 %0, %1;" : "=r"(u) : "f"(f));
    return u;
}
__device__ __forceinline__ float rnatf(float f) { return __uint_as_float(f2tf(f)); }

// float-index of element (row r in 128-row tile st, col k) of expert e in fragment layout.
// KQ = K/8 quads. Fragment: [e*32+st][ksq][t16][lane][q] ; lane=((r&7)<<2)|(k&3),
// q = bit3(r) | bit2(k)<<1  -> matches mma.m16n8k8 A-fragment (a0..a3).
__device__ __forceinline__ size_t frag_off(int e, int st, int KQ, int r, int k) {
    size_t blk = (((size_t)(e * 32 + st) * KQ + (k >> 3)) * 8 + (r >> 4)) * 128;
    int lane = ((r & 7) << 2) | (k & 3);
    int q = ((r >> 3) & 1) | (((k >> 2) & 1) << 1);
    return blk + (size_t)(lane << 2) + q;
}

__device__ __forceinline__ void mma8v(float* c, const uint4& a, const uint32_t* b) {
    asm volatile(
        "mma.sync.aligned.m16n8k8.row.col.f32.tf32.tf32.f32 "
        "{%0,%1,%2,%3}, {%4,%5,%6,%7}, {%8,%9}, {%0,%1,%2,%3};"
        : "+f"(c[0]), "+f"(c[1]), "+f"(c[2]), "+f"(c[3])
        : "r"(a.x), "r"(a.y), "r"(a.z), "r"(a.w), "r"(b[0]), "r"(b[1]));
}

__device__ __forceinline__ float gelu_exact(float v) {
    return 0.5f * v * (1.0f + erff(v * 0.70710678118654752f));
}

// ---------------- kernel 1: gate scores, combine weights, out init with sum(c*b2) ----------------
__global__ __launch_bounds__(256) void gate_kernel(
    const float* __restrict__ x, const float* __restrict__ wg,
    const float* __restrict__ bg, const float* __restrict__ b2,
    float* __restrict__ out)
{
    __shared__ float wgs[DIM * 9];
    int tid = threadIdx.x;
    for (int i = tid; i < DIM * NEXP; i += 256)
        wgs[(i >> 3) * 9 + (i & 7)] = wg[i];
    __syncthreads();

    int lane = tid & 31, wid = tid >> 5;
    int n = blockIdx.x * 8 + wid;

    float s[NEXP];
#pragma unroll
    for (int e = 0; e < NEXP; e++) s[e] = 0.f;

    const float* xr = x + (size_t)n * DIM;
    for (int k = lane; k < DIM; k += 32) {
        float xv = xr[k];
#pragma unroll
        for (int e = 0; e < NEXP; e++) s[e] += xv * wgs[k * 9 + e];
    }
#pragma unroll
    for (int e = 0; e < NEXP; e++)
#pragma unroll
        for (int o = 16; o; o >>= 1)
            s[e] += __shfl_xor_sync(0xffffffffu, s[e], o);

    float mx = -1e30f;
#pragma unroll
    for (int e = 0; e < NEXP; e++) { s[e] += bg[e]; mx = fmaxf(mx, s[e]); }
    float sum = 0.f;
#pragma unroll
    for (int e = 0; e < NEXP; e++) { s[e] = expf(s[e] - mx); sum += s[e]; }
    float inv = 1.f / sum;
#pragma unroll
    for (int e = 0; e < NEXP; e++) s[e] *= inv;

    if (lane == 0) {
        float* gs = out + (size_t)NTOK * DIM + (size_t)n * NEXP;
#pragma unroll
        for (int e = 0; e < NEXP; e++) gs[e] = s[e];
    }

    float msum = 0.f; int cnt = 0;
#pragma unroll
    for (int e = 0; e < NEXP; e++) if (s[e] >= THR) { msum += s[e]; cnt++; }
    int top1 = 0; float best = s[0];
#pragma unroll
    for (int e = 1; e < NEXP; e++) if (s[e] > best) { best = s[e]; top1 = e; }
    float dn = 1.f / (msum + 1e-6f);
    float c[NEXP];
#pragma unroll
    for (int e = 0; e < NEXP; e++)
        c[e] = cnt ? ((s[e] >= THR) ? s[e] * dn : 0.f) : ((e == top1) ? 1.f : 0.f);

    if (lane == 0) {
#pragma unroll
        for (int e = 0; e < NEXP; e++) g_c[n * NEXP + e] = c[e];
    }

    for (int d = lane; d < DIM; d += 32) {
        float a = 0.f;
#pragma unroll
        for (int e = 0; e < NEXP; e++) a += c[e] * b2[e * DIM + d];
        out[(size_t)n * DIM + d] = a;
    }
}

// ---------------- kernel 2: per-expert compaction, 1 CTA per expert ----------------
__global__ __launch_bounds__(256) void compact_kernel()
{
    const int e = blockIdx.x;
    __shared__ int wsum[8];
    __shared__ int wbase[9];
    const int tid = threadIdx.x, lane = tid & 31, wid = tid >> 5;

    int base = 0;
#pragma unroll
    for (int c0 = 0; c0 < NTOK; c0 += 256) {
        int n = c0 + tid;
        float c = g_c[n * NEXP + e];
        unsigned m = __ballot_sync(0xffffffffu, c > 0.f);
        if (lane == 0) wsum[wid] = __popc(m);
        __syncthreads();
        if (tid == 0) {
            int acc = 0;
#pragma unroll
            for (int w = 0; w < 8; w++) { wbase[w] = acc; acc += wsum[w]; }
            wbase[8] = acc;
        }
        __syncthreads();
        if (c > 0.f) {
            int pos = base + wbase[wid] + __popc(m & ((1u << lane) - 1u));
            g_idx[e][pos] = n;
            g_wt[e][pos]  = c;
        }
        base += wbase[8];
        __syncthreads();
    }
    if (tid == 0) g_cnt[e] = base;
}

// ---------------- kernel 2b: gather + tf32-round expert inputs into fragment layout ----------------
__global__ __launch_bounds__(256) void permA_kernel(const float* __restrict__ ei)
{
    const int st = blockIdx.x;
    const int e  = blockIdx.y;
    const int me = g_cnt[e];
    if (st * BM >= me) return;
    const int tid  = threadIdx.x;
    const int r    = tid >> 1;          // 0..127 row in tile
    const int half = tid & 1;           // 0..1: k halves of 512
    const int ss = st * BM + r;
    if (ss >= me) return;
    const int tok = g_idx[e][ss];
    const float4* src = (const float4*)(ei + ((size_t)e * NTOK + tok) * DIM) + half * 128;

#pragma unroll 4
    for (int kq = 0; kq < 128; kq++) {
        int k = half * 512 + kq * 4;
        float4 v = src[kq];
        size_t o = frag_off(e, st, DIM / 8, r, k);
        g_af[o +  0] = rnatf(v.x);
        g_af[o +  4] = rnatf(v.y);
        g_af[o +  8] = rnatf(v.z);
        g_af[o + 12] = rnatf(v.w);
    }
}

// =====================================================================================
// FFN GEMMs: 4 warps/CTA, warp tile 64x64, CTA tile 128x128, BK=16.
// A: direct fragment LDG.128 from permuted global (no smem). B: double-buffered smem.
// =====================================================================================

// ---------------- kernel 3: grouped GEMM1: hf = frag(gelu(A @ w1 + b1)) ----------------
__global__ __launch_bounds__(128, 2) void ffn1_kernel(
    const float* __restrict__ w1, const float* __restrict__ b1)
{
    __shared__ float Bs[2 * STG];

    const int e  = blockIdx.z;
    const int me = g_cnt[e];
    const int mt = blockIdx.x;
    if (mt * BM >= me) return;
    const int n0 = blockIdx.y * BN;

    const int tid  = threadIdx.x;
    const int lane = tid & 31;
    const int wid  = tid >> 5;
    const int wm   = wid >> 1;
    const int wn   = wid & 1;
    const int g    = lane >> 2;
    const int t    = lane & 3;

    // A fragment base (uint4 units)
    const uint4* aF = (const uint4*)g_af;
    const size_t aBase = (((size_t)(e * 32 + mt) * (DIM / 8)) * 8 + wm * 4) * 32 + lane;

    // B loader (as R4)
    const int bk4 = wid * 4;
    const float* bptr = w1 + (size_t)e * DIM * HID + n0 + lane * 4;
    const int bofs = (lane >> 1) * 136 + 4 * (lane & 1);

    float acc[4][8][4];
#pragma unroll
    for (int a = 0; a < 4; a++)
#pragma unroll
        for (int b = 0; b < 8; b++)
#pragma unroll
            for (int q = 0; q < 4; q++) acc[a][b][q] = 0.f;

    uint4 afc[2][4], afn[2][4];
    float4 pb[4];

    // prime
#pragma unroll
    for (int ks = 0; ks < 2; ks++)
#pragma unroll
        for (int mi = 0; mi < 4; mi++)
            afc[ks][mi] = aF[aBase + (size_t)ks * 256 + mi * 32];
#pragma unroll
    for (int i = 0; i < 4; i++)
        pb[i] = *(const float4*)(bptr + (size_t)(bk4 + i) * HID);
#pragma unroll
    for (int i = 0; i < 4; i++) {
        float4 v = make_float4(rnatf(pb[i].x), rnatf(pb[i].y), rnatf(pb[i].z), rnatf(pb[i].w));
        *(float4*)(Bs + bofs + (bk4 + i) * 8) = v;
    }
    __syncthreads();

    const int KT = DIM / BK;   // 64
    for (int kt = 0; kt < KT; kt++) {
        const int cur = (kt & 1) * STG;
        const bool more = (kt + 1 < KT);
        if (more) {
#pragma unroll
            for (int ks = 0; ks < 2; ks++)
#pragma unroll
                for (int mi = 0; mi < 4; mi++)
                    afn[ks][mi] = aF[aBase + (size_t)((kt + 1) * 2 + ks) * 256 + mi * 32];
            const float* bp = bptr + (size_t)(kt + 1) * BK * HID;
#pragma unroll
            for (int i = 0; i < 4; i++)
                pb[i] = *(const float4*)(bp + (size_t)(bk4 + i) * HID);
        }
#pragma unroll
        for (int ks = 0; ks < 2; ks++) {
            const int k0 = ks * 8;
#pragma unroll
            for (int ni = 0; ni < 8; ni++) {
                int G = wn * 8 + ni;
                uint32_t bf[2];
                bf[0] = __float_as_uint(Bs[cur + G * 136 + (k0 + t) * 8 + g]);
                bf[1] = __float_as_uint(Bs[cur + G * 136 + (k0 + t + 4) * 8 + g]);
#pragma unroll
                for (int mi = 0; mi < 4; mi++)
                    mma8v(acc[mi][ni], afc[ks][mi], bf);
            }
        }
        if (more) {
            const int nxt = ((kt + 1) & 1) * STG;
#pragma unroll
            for (int i = 0; i < 4; i++) {
                float4 v = make_float4(rnatf(pb[i].x), rnatf(pb[i].y), rnatf(pb[i].z), rnatf(pb[i].w));
                *(float4*)(Bs + nxt + bofs + (bk4 + i) * 8) = v;
            }
#pragma unroll
            for (int ks = 0; ks < 2; ks++)
#pragma unroll
                for (int mi = 0; mi < 4; mi++)
                    afc[ks][mi] = afn[ks][mi];
        }
        __syncthreads();
    }

    // epilogue: +b1, exact GELU, rna-round, write hidden in fragment layout
#pragma unroll
    for (int mi = 0; mi < 4; mi++) {
#pragma unroll
        for (int h2 = 0; h2 < 2; h2++) {
            int row = wm * 64 + mi * 16 + g + 8 * h2;
            int ss = mt * BM + row;
            if (ss < me) {
#pragma unroll
                for (int ni = 0; ni < 8; ni++) {
                    int colb = n0 + wn * 64 + ni * 8 + 2 * t;
                    float b0v = b1[e * HID + colb];
                    float b1v = b1[e * HID + colb + 1];
                    float v0 = rnatf(gelu_exact(acc[mi][ni][2 * h2 + 0] + b0v));
                    float v1 = rnatf(gelu_exact(acc[mi][ni][2 * h2 + 1] + b1v));
                    g_hf[frag_off(e, mt, HID / 8, row, colb)]     = v0;
                    g_hf[frag_off(e, mt, HID / 8, row, colb + 1)] = v1;
                }
            }
        }
    }
}

// ---------------- kernel 4: grouped GEMM2 (K-split x4): out[tok] += c * (hf @ w2) ----------------
__global__ __launch_bounds__(128, 2) void ffn2_kernel(
    const float* __restrict__ w2, float* __restrict__ out)
{
    __shared__ float Bs[2 * STG];

    const int e  = blockIdx.z >> 2;
    const int sp = blockIdx.z & 3;
    const int me = g_cnt[e];
    const int mt = blockIdx.x;
    if (mt * BM >= me) return;
    const int n0 = blockIdx.y * BN;

    const int tid  = threadIdx.x;
    const int lane = tid & 31;
    const int wid  = tid >> 5;
    const int wm   = wid >> 1;
    const int wn   = wid & 1;
    const int g    = lane >> 2;
    const int t    = lane & 3;

    // A fragment base (uint4 units), k offset = sp*1024 -> ksq0 = sp*128
    const uint4* aF = (const uint4*)g_hf;
    const size_t aBase = (((size_t)(e * 32 + mt) * (HID / 8) + sp * 128) * 8 + wm * 4) * 32 + lane;

    const int bk4 = wid * 4;
    const float* bptr = w2 + (size_t)e * HID * DIM + (size_t)sp * 1024 * DIM + n0 + lane * 4;
    const int bofs = (lane >> 1) * 136 + 4 * (lane & 1);

    float acc[4][8][4];
#pragma unroll
    for (int a = 0; a < 4; a++)
#pragma unroll
        for (int b = 0; b < 8; b++)
#pragma unroll
            for (int q = 0; q < 4; q++) acc[a][b][q] = 0.f;

    uint4 afc[2][4], afn[2][4];
    float4 pb[4];

#pragma unroll
    for (int ks = 0; ks < 2; ks++)
#pragma unroll
        for (int mi = 0; mi < 4; mi++)
            afc[ks][mi] = aF[aBase + (size_t)ks * 256 + mi * 32];
#pragma unroll
    for (int i = 0; i < 4; i++)
        pb[i] = *(const float4*)(bptr + (size_t)(bk4 + i) * DIM);
#pragma unroll
    for (int i = 0; i < 4; i++) {
        float4 v = make_float4(rnatf(pb[i].x), rnatf(pb[i].y), rnatf(pb[i].z), rnatf(pb[i].w));
        *(float4*)(Bs + bofs + (bk4 + i) * 8) = v;
    }
    __syncthreads();

    const int KT = 1024 / BK;   // 64 per split
    for (int kt = 0; kt < KT; kt++) {
        const int cur = (kt & 1) * STG;
        const bool more = (kt + 1 < KT);
        if (more) {
#pragma unroll
            for (int ks = 0; ks < 2; ks++)
#pragma unroll
                for (int mi = 0; mi < 4; mi++)
                    afn[ks][mi] = aF[aBase + (size_t)((kt + 1) * 2 + ks) * 256 + mi * 32];
            const float* bp = bptr + (size_t)(kt + 1) * BK * DIM;
#pragma unroll
            for (int i = 0; i < 4; i++)
                pb[i] = *(const float4*)(bp + (size_t)(bk4 + i) * DIM);
        }
#pragma unroll
        for (int ks = 0; ks < 2; ks++) {
            const int k0 = ks * 8;
#pragma unroll
            for (int ni = 0; ni < 8; ni++) {
                int G = wn * 8 + ni;
                uint32_t bf[2];
                bf[0] = __float_as_uint(Bs[cur + G * 136 + (k0 + t) * 8 + g]);
                bf[1] = __float_as_uint(Bs[cur + G * 136 + (k0 + t + 4) * 8 + g]);
#pragma unroll
                for (int mi = 0; mi < 4; mi++)
                    mma8v(acc[mi][ni], afc[ks][mi], bf);
            }
        }
        if (more) {
            const int nxt = ((kt + 1) & 1) * STG;
#pragma unroll
            for (int i = 0; i < 4; i++) {
                float4 v = make_float4(rnatf(pb[i].x), rnatf(pb[i].y), rnatf(pb[i].z), rnatf(pb[i].w));
                *(float4*)(Bs + nxt + bofs + (bk4 + i) * 8) = v;
            }
#pragma unroll
            for (int ks = 0; ks < 2; ks++)
#pragma unroll
                for (int mi = 0; mi < 4; mi++)
                    afc[ks][mi] = afn[ks][mi];
        }
        __syncthreads();
    }

    // epilogue: scaled scatter-add into fused output (split partials just add)
#pragma unroll
    for (int mi = 0; mi < 4; mi++) {
#pragma unroll
        for (int h2 = 0; h2 < 2; h2++) {
            int row = wm * 64 + mi * 16 + g + 8 * h2;
            int ss = mt * BM + row;
            if (ss < me) {
                int tok  = g_idx[e][ss];
                float wc = g_wt[e][ss];
                float* orow = out + (size_t)tok * DIM;
#pragma unroll
                for (int ni = 0; ni < 8; ni++) {
                    int col = n0 + wn * 64 + ni * 8 + 2 * t;
                    atomicAdd(orow + col,     wc * acc[mi][ni][2 * h2 + 0]);
                    atomicAdd(orow + col + 1, wc * acc[mi][ni][2 * h2 + 1]);
                }
            }
        }
    }
}

// ---------------- launch ----------------
extern "C" void kernel_launch(void* const* d_in, const int* in_sizes, int n_in,
                              void* d_out, int out_size)
{
    (void)in_sizes; (void)n_in; (void)out_size;
    const float* x  = (const float*)d_in[0];
    const float* ei = (const float*)d_in[1];
    const float* wg = (const float*)d_in[2];
    const float* bg = (const float*)d_in[3];
    const float* w1 = (const float*)d_in[4];
    const float* b1 = (const float*)d_in[5];
    const float* w2 = (const float*)d_in[6];
    const float* b2 = (const float*)d_in[7];
    float* out = (float*)d_out;

    gate_kernel<<<NTOK / 8, 256>>>(x, wg, bg, b2, out);
    compact_kernel<<<NEXP, 256>>>();
    permA_kernel<<<dim3(NTOK / BM, NEXP), 256>>>(ei);
    ffn1_kernel<<<dim3(NTOK / BM, HID / BN, NEXP), 128>>>(w1, b1);
    ffn2_kernel<<<dim3(NTOK / BM, DIM / BN, NEXP * 4), 128>>>(w2, out);
}